// round 10
// baseline (speedup 1.0000x reference)
#include <cuda_runtime.h>
#include <cuda_fp16.h>
#include <math.h>

#define NHN 50000
#define NON 50000
#define NEN 500000
#define DN  256
#define LN  8
#define BNB 512
#define CNC 117

// ---------------- device scratch (static: allocation-free rule) ----------------
__device__ __align__(16) float g_xh[2][NHN*DN];
__device__ __align__(16) float g_xo[2][NON*DN];
__device__ __align__(16) float g_agg_h[NHN*DN];
__device__ __align__(16) float g_agg_o[NON*DN];
__device__ float g_ex_ho[NEN];
__device__ float g_ex_oh[NEN];
__device__ float g_as_ho[NHN];
__device__ float g_ad_ho[NON];
__device__ float g_as_oh[NON];
__device__ float g_ad_oh[NHN];
__device__ float g_den_ho[NON];
__device__ float g_den_oh[NHN];
__device__ __align__(16) float g_wvec[4][DN];
__device__ float g_cvec[4];
__device__ __align__(16) float g_hpool[BNB*DN];
__device__ __align__(16) float g_opool[BNB*DN];
__device__ float g_epool[BNB*32];
__device__ int g_starts_h[BNB+1];
__device__ int g_starts_o[BNB+1];
__device__ int g_cnt_e[BNB];
// fp16-split staging buffers (packed half2 along K)
__device__ __align__(16) unsigned g_Wh[2*LN*(DN/2)*DN];   // 2 MB
__device__ __align__(16) unsigned g_Wl[2*LN*(DN/2)*DN];
__device__ __align__(16) unsigned g_Ahh[NHN*(DN/2)];      // 25.6 MB
__device__ __align__(16) unsigned g_All[NHN*(DN/2)];

// ---------------- helpers ----------------
__device__ __forceinline__ void red_add4(float* p, float4 v) {
    asm volatile("red.global.add.v4.f32 [%0], {%1,%2,%3,%4};"
                 :: "l"(p), "f"(v.x), "f"(v.y), "f"(v.z), "f"(v.w) : "memory");
}
// split (a,b) -> packed half2 hi + half2 lo (2-term fp16 split, 22-bit effective)
__device__ __forceinline__ void split2(float a, float b, unsigned &hi, unsigned &lo) {
    __half ha = __float2half_rn(a), hb = __float2half_rn(b);
    __half la = __float2half_rn(a - __half2float(ha));
    __half lb = __float2half_rn(b - __half2float(hb));
    hi = (unsigned)__half_as_ushort(ha) | ((unsigned)__half_as_ushort(hb) << 16);
    lo = (unsigned)__half_as_ushort(la) | ((unsigned)__half_as_ushort(lb) << 16);
}
__device__ __forceinline__ void mma_f16(float* d, const unsigned* a, const unsigned* b) {
    asm volatile("mma.sync.aligned.m16n8k16.row.col.f32.f16.f16.f32 "
                 "{%0,%1,%2,%3}, {%4,%5,%6,%7}, {%8,%9}, {%0,%1,%2,%3};"
                 : "+f"(d[0]), "+f"(d[1]), "+f"(d[2]), "+f"(d[3])
                 : "r"(a[0]), "r"(a[1]), "r"(a[2]), "r"(a[3]),
                   "r"(b[0]), "r"(b[1]));
}
__device__ __forceinline__ void cp16(unsigned* dst, const unsigned* src) {
    unsigned d = (unsigned)__cvta_generic_to_shared(dst);
    asm volatile("cp.async.cg.shared.global [%0], [%1], 16;" :: "r"(d), "l"(src));
}
__device__ __forceinline__ void cp16z(unsigned* dst, const unsigned* src, int sz) {
    unsigned d = (unsigned)__cvta_generic_to_shared(dst);
    asm volatile("cp.async.cg.shared.global [%0], [%1], 16, %2;" :: "r"(d), "l"(src), "r"(sz));
}
#define CP_COMMIT() asm volatile("cp.async.commit_group;")

// ---------------- weight pre-split: all 16 matrices -> packed half2 hi/lo
// layout per matrix: word (k2, n) = half2(W[2k2][n], W[2k2+1][n]), index k2*DN + n
__global__ void k_convW(const float* __restrict__ Who, const float* __restrict__ Woh)
{
    int t = blockIdx.x * blockDim.x + threadIdx.x;      // 16*128*64 = 131072
    int m  = t >> 13;                                    // matrix 0..15
    int r  = t & 8191;
    int k2 = r >> 6;                                     // 0..127
    int ng = r & 63;                                     // n group (4 cols)
    const float* W = ((m >> 3) ? Woh : Who) + (size_t)(m & 7) * DN * DN;
    float4 u0 = *(const float4*)&W[(size_t)(2*k2)     * DN + ng*4];
    float4 u1 = *(const float4*)&W[(size_t)(2*k2 + 1) * DN + ng*4];
    uint4 hi, lo;
    split2(u0.x, u1.x, hi.x, lo.x);
    split2(u0.y, u1.y, hi.y, lo.y);
    split2(u0.z, u1.z, hi.z, lo.z);
    split2(u0.w, u1.w, hi.w, lo.w);
    size_t o = (size_t)m * ((DN/2)*DN) + (size_t)k2 * DN + ng*4;
    *(uint4*)&g_Wh[o] = hi;
    *(uint4*)&g_Wl[o] = lo;
}

// ---------------- A pre-split: fp32 row-major -> packed half2 hi/lo
__global__ void k_convA(const float* __restrict__ A, unsigned* __restrict__ Ah,
                        unsigned* __restrict__ Al, int n8)
{
    int t = blockIdx.x * blockDim.x + threadIdx.x;   // each handles 8 floats
    if (t >= n8) return;
    const float4* p = (const float4*)A + (size_t)t * 2;
    float4 v0 = p[0], v1 = p[1];
    uint4 hi, lo;
    split2(v0.x, v0.y, hi.x, lo.x);
    split2(v0.z, v0.w, hi.y, lo.y);
    split2(v1.x, v1.y, hi.z, lo.z);
    split2(v1.z, v1.w, hi.w, lo.w);
    *(uint4*)(Ah + (size_t)t * 4) = hi;
    *(uint4*)(Al + (size_t)t * 4) = lo;
}

// ---------------- per-layer small weights
__global__ void k_small(const float* WsrcHo, const float* asrcHo,
                        const float* WdstHo, const float* adstHo,
                        const float* WsrcOh, const float* asrcOh,
                        const float* WdstOh, const float* adstOh,
                        const float* WedgeHo, const float* aedgeHo,
                        const float* WedgeOh, const float* aedgeOh, int l)
{
    int k = threadIdx.x;
    const float* W0 = WsrcHo + (size_t)l*DN*DN + (size_t)k*DN;
    const float* W1 = WdstHo + (size_t)l*DN*DN + (size_t)k*DN;
    const float* W2 = WsrcOh + (size_t)l*DN*DN + (size_t)k*DN;
    const float* W3 = WdstOh + (size_t)l*DN*DN + (size_t)k*DN;
    const float* a0 = asrcHo + l*DN;
    const float* a1 = adstHo + l*DN;
    const float* a2 = asrcOh + l*DN;
    const float* a3 = adstOh + l*DN;
    float s0 = 0.f, s1 = 0.f, s2 = 0.f, s3 = 0.f;
    for (int n = 0; n < DN; n++) {
        s0 += W0[n] * a0[n];
        s1 += W1[n] * a1[n];
        s2 += W2[n] * a2[n];
        s3 += W3[n] * a3[n];
    }
    g_wvec[0][k] = s0; g_wvec[1][k] = s1; g_wvec[2][k] = s2; g_wvec[3][k] = s3;
    if (k < 2) {
        float c = 0.f;
        const float* We = WedgeHo + (size_t)l*2*DN + (size_t)k*DN;
        const float* ae = aedgeHo + l*DN;
        for (int n = 0; n < DN; n++) c += We[n] * ae[n];
        g_cvec[k] = c;
    } else if (k < 4) {
        int r = k - 2;
        float c = 0.f;
        const float* We = WedgeOh + (size_t)l*2*DN + (size_t)r*DN;
        const float* ae = aedgeOh + l*DN;
        for (int n = 0; n < DN; n++) c += We[n] * ae[n];
        g_cvec[k] = c;
    }
}

// ---------------- node scores: two dot products per node (warp per node)
__global__ void k_nodescore(const float* __restrict__ x, int ia, int ib,
                            float* __restrict__ outA, float* __restrict__ outB, int N)
{
    int w = (blockIdx.x * blockDim.x + threadIdx.x) >> 5;
    int lane = threadIdx.x & 31;
    if (w >= N) return;
    const float4* xr = (const float4*)(x + (size_t)w * DN);
    const float4* va = (const float4*)g_wvec[ia];
    const float4* vb = (const float4*)g_wvec[ib];
    float4 x0 = xr[lane], x1 = xr[lane + 32];
    float4 a0 = va[lane], a1 = va[lane + 32];
    float4 b0 = vb[lane], b1 = vb[lane + 32];
    float dA = x0.x*a0.x + x0.y*a0.y + x0.z*a0.z + x0.w*a0.w
             + x1.x*a1.x + x1.y*a1.y + x1.z*a1.z + x1.w*a1.w;
    float dB = x0.x*b0.x + x0.y*b0.y + x0.z*b0.z + x0.w*b0.w
             + x1.x*b1.x + x1.y*b1.y + x1.z*b1.z + x1.w*b1.w;
    #pragma unroll
    for (int off = 16; off > 0; off >>= 1) {
        dA += __shfl_down_sync(0xffffffffu, dA, off);
        dB += __shfl_down_sync(0xffffffffu, dB, off);
    }
    if (lane == 0) { outA[w] = dA; outB[w] = dB; }
}

// ---------------- fused edge pass: logit -> exp + segment sum
__global__ void k_edgeAB(const int* __restrict__ src, const int* __restrict__ dst,
                         const float* __restrict__ ea,
                         const float* __restrict__ a_s, const float* __restrict__ a_d,
                         const float* __restrict__ cpair,
                         float* __restrict__ ex, float* __restrict__ den)
{
    int e = blockIdx.x * blockDim.x + threadIdx.x;
    if (e >= NEN) return;
    int s = src[e], d = dst[e];
    float2 at = ((const float2*)ea)[e];
    float lg = a_s[s] + a_d[d] + at.x * cpair[0] + at.y * cpair[1];
    lg = (lg > 0.f) ? lg : 0.2f * lg;
    float v = __expf(lg);
    ex[e] = v;
    atomicAdd(&den[d], v);
}

// ---------------- edge pass C: weighted gather + scatter-add (warp per edge)
__global__ void k_edgeC(const int* __restrict__ src, const int* __restrict__ dst,
                        const float* __restrict__ ex, const float* __restrict__ den,
                        const float* __restrict__ x, float* __restrict__ agg)
{
    int e = (blockIdx.x * blockDim.x + threadIdx.x) >> 5;
    if (e >= NEN) return;
    int lane = threadIdx.x & 31;
    int s = src[e], d = dst[e];
    float w = ex[e] / den[d];
    const float4* xs = (const float4*)(x + (size_t)s * DN);
    float4 v0 = xs[lane], v1 = xs[lane + 32];
    v0.x *= w; v0.y *= w; v0.z *= w; v0.w *= w;
    v1.x *= w; v1.y *= w; v1.z *= w; v1.w *= w;
    float* base = agg + (size_t)d * DN;
    red_add4(base + lane * 4, v0);
    red_add4(base + 128 + lane * 4, v1);
}

// ---------------- tensor-core GEMM v3: pre-split fp16 hi/lo inputs, cp.async double buffer
// out = relu(A@W + bias) [+ resid]; 128x128 tile, BK=32 (16 half2 words), 8 warps (2x4)
#define ASTR2 20
#define BSTR2 132
#define ASZ (128*ASTR2)
#define BSZ (16*BSTR2)
#define NCH (DN/32)
#define GSMEM ((4*ASZ + 4*BSZ) * 4)   // 74752 bytes

__global__ void __launch_bounds__(256, 2)
k_gemm_tc(const unsigned* __restrict__ Ah, const unsigned* __restrict__ Al,
          const unsigned* __restrict__ Wh, const unsigned* __restrict__ Wl,
          const float* __restrict__ bias, const float* __restrict__ resid,
          float* __restrict__ Cmat, int M)
{
    extern __shared__ unsigned sm[];
    unsigned* sAh = sm;
    unsigned* sAl = sm + 2*ASZ;
    unsigned* sBh = sm + 4*ASZ;
    unsigned* sBl = sm + 4*ASZ + 2*BSZ;

    int tid  = threadIdx.x;
    int lane = tid & 31;
    int warp = tid >> 5;
    int wRow = warp >> 2;
    int wCol = warp & 3;
    int rowBase = blockIdx.y * 128;
    int colBase = blockIdx.x * 128;

    float acc[4][4][4];
    #pragma unroll
    for (int i = 0; i < 4; i++)
        #pragma unroll
        for (int j = 0; j < 4; j++)
            #pragma unroll
            for (int k = 0; k < 4; k++) acc[i][j][k] = 0.f;

    int arow = tid >> 1, aoff = (tid & 1) * 8;
    int bk2  = tid >> 4, boff = (tid & 15) * 8;
    int gr = rowBase + arow;
    const unsigned* gAh = Ah + (size_t)gr * (DN/2) + aoff;
    const unsigned* gAl = Al + (size_t)gr * (DN/2) + aoff;
    int apred = (gr < M) ? 16 : 0;
    const unsigned* gBh = Wh + (size_t)bk2 * DN + colBase + boff;
    const unsigned* gBl = Wl + (size_t)bk2 * DN + colBase + boff;
    unsigned* dAh = sAh + arow * ASTR2 + aoff;
    unsigned* dAl = sAl + arow * ASTR2 + aoff;
    unsigned* dBh = sBh + bk2 * BSTR2 + boff;
    unsigned* dBl = sBl + bk2 * BSTR2 + boff;

    #define STAGE(b, c) do { \
        cp16z(dAh + (b)*ASZ,     gAh + (c)*16,     apred); \
        cp16z(dAh + (b)*ASZ + 4, gAh + (c)*16 + 4, apred); \
        cp16z(dAl + (b)*ASZ,     gAl + (c)*16,     apred); \
        cp16z(dAl + (b)*ASZ + 4, gAl + (c)*16 + 4, apred); \
        cp16(dBh + (b)*BSZ,     gBh + (size_t)(c)*16*DN); \
        cp16(dBh + (b)*BSZ + 4, gBh + (size_t)(c)*16*DN + 4); \
        cp16(dBl + (b)*BSZ,     gBl + (size_t)(c)*16*DN); \
        cp16(dBl + (b)*BSZ + 4, gBl + (size_t)(c)*16*DN + 4); \
        CP_COMMIT(); \
    } while (0)

    STAGE(0, 0);
    int buf = 0;
    for (int c = 0; c < NCH; c++) {
        if (c + 1 < NCH) {
            STAGE(buf ^ 1, c + 1);
            asm volatile("cp.async.wait_group 1;" ::: "memory");
        } else {
            asm volatile("cp.async.wait_group 0;" ::: "memory");
        }
        __syncthreads();
        const unsigned* Abh = sAh + buf * ASZ;
        const unsigned* Abl = sAl + buf * ASZ;
        const unsigned* Bbh = sBh + buf * BSZ;
        const unsigned* Bbl = sBl + buf * BSZ;
        #pragma unroll
        for (int s = 0; s < 2; s++) {
            int kk = s * 8 + (lane & 3);
            unsigned bhf[4][2], blf[4][2];
            #pragma unroll
            for (int nt = 0; nt < 4; nt++) {
                int n = wCol * 32 + nt * 8 + (lane >> 2);
                bhf[nt][0] = Bbh[kk * BSTR2 + n];       bhf[nt][1] = Bbh[(kk + 4) * BSTR2 + n];
                blf[nt][0] = Bbl[kk * BSTR2 + n];       blf[nt][1] = Bbl[(kk + 4) * BSTR2 + n];
            }
            #pragma unroll
            for (int mt = 0; mt < 4; mt++) {
                int r = wRow * 64 + mt * 16 + (lane >> 2);
                unsigned ahf[4], alf[4];
                ahf[0] = Abh[r * ASTR2 + kk];           ahf[1] = Abh[(r + 8) * ASTR2 + kk];
                ahf[2] = Abh[r * ASTR2 + kk + 4];       ahf[3] = Abh[(r + 8) * ASTR2 + kk + 4];
                alf[0] = Abl[r * ASTR2 + kk];           alf[1] = Abl[(r + 8) * ASTR2 + kk];
                alf[2] = Abl[r * ASTR2 + kk + 4];       alf[3] = Abl[(r + 8) * ASTR2 + kk + 4];
                #pragma unroll
                for (int nt = 0; nt < 4; nt++) {
                    mma_f16(acc[mt][nt], ahf, bhf[nt]);
                    mma_f16(acc[mt][nt], ahf, blf[nt]);
                    mma_f16(acc[mt][nt], alf, bhf[nt]);
                }
            }
        }
        __syncthreads();
        buf ^= 1;
    }

    // ---- epilogue: bias + relu [+ resid]
    #pragma unroll
    for (int mt = 0; mt < 4; mt++) {
        int r = rowBase + wRow * 64 + mt * 16 + (lane >> 2);
        #pragma unroll
        for (int nt = 0; nt < 4; nt++) {
            int c = colBase + wCol * 32 + nt * 8 + (lane & 3) * 2;
            float b0 = bias[c], b1 = bias[c + 1];
            if (r < M) {
                float v0 = fmaxf(acc[mt][nt][0] + b0, 0.f);
                float v1 = fmaxf(acc[mt][nt][1] + b1, 0.f);
                if (resid) {
                    float2 rv = *(const float2*)&resid[(size_t)r * DN + c];
                    v0 += rv.x; v1 += rv.y;
                }
                *(float2*)&Cmat[(size_t)r * DN + c] = make_float2(v0, v1);
            }
            int r2 = r + 8;
            if (r2 < M) {
                float v2 = fmaxf(acc[mt][nt][2] + b0, 0.f);
                float v3 = fmaxf(acc[mt][nt][3] + b1, 0.f);
                if (resid) {
                    float2 rv = *(const float2*)&resid[(size_t)r2 * DN + c];
                    v2 += rv.x; v3 += rv.y;
                }
                *(float2*)&Cmat[(size_t)r2 * DN + c] = make_float2(v2, v3);
            }
        }
    }
}

// ---------------- batch segment boundaries from sorted batch vector
__global__ void k_starts(const int* __restrict__ batch, int* __restrict__ starts, int N)
{
    int i = blockIdx.x * blockDim.x + threadIdx.x;
    if (i >= N) return;
    int b = batch[i];
    int prev = (i == 0) ? -1 : batch[i - 1];
    for (int v = prev + 1; v <= b; v++) starts[v] = i;
    if (i == N - 1)
        for (int v = b + 1; v <= BNB; v++) starts[v] = N;
}

// ---------------- segment-mean pooling (block per batch, thread per column)
__global__ void k_pool(const float* __restrict__ x, const int* __restrict__ starts,
                       float* __restrict__ pool)
{
    int b = blockIdx.x, c = threadIdx.x;
    int s0 = starts[b], s1 = starts[b + 1];
    float acc = 0.f;
    for (int i = s0; i < s1; i++) acc += x[(size_t)i * DN + c];
    pool[b * DN + c] = acc / fmaxf((float)(s1 - s0), 1.f);
}

// ---------------- edge MLP pooling (warp per edge, lane per output channel)
__global__ void k_epool(const int* __restrict__ src, const float* __restrict__ ea,
                        const int* __restrict__ hbatch,
                        const float* __restrict__ Wem, const float* __restrict__ bem)
{
    __shared__ int hist[BNB];
    for (int t = threadIdx.x; t < BNB; t += blockDim.x) hist[t] = 0;
    __syncthreads();
    int lane = threadIdx.x & 31;
    int wid = (blockIdx.x * blockDim.x + threadIdx.x) >> 5;
    int nw = (gridDim.x * blockDim.x) >> 5;
    float w0 = Wem[lane], w1 = Wem[32 + lane], bb = bem[lane];
    for (int e = wid; e < NEN; e += nw) {
        int b = hbatch[src[e]];
        float2 at = ((const float2*)ea)[e];
        float v = fmaxf(at.x * w0 + at.y * w1 + bb, 0.f);
        atomicAdd(&g_epool[b * 32 + lane], v);
        if (lane == 0) atomicAdd(&hist[b], 1);
    }
    __syncthreads();
    for (int t = threadIdx.x; t < BNB; t += blockDim.x)
        if (hist[t]) atomicAdd(&g_cnt_e[t], hist[t]);
}

__global__ void k_epool_div()
{
    int i = blockIdx.x * blockDim.x + threadIdx.x;
    if (i >= BNB * 32) return;
    g_epool[i] /= fmaxf((float)g_cnt_e[i >> 5], 1.f);
}

// ---------------- final heads: linear + softmax (block per (batch, head))
__global__ void k_head(const float* __restrict__ Wp1, const float* __restrict__ bp1,
                       const float* __restrict__ Wp2, const float* __restrict__ bp2,
                       float* __restrict__ out)
{
    __shared__ float emb[2*DN + 32];
    __shared__ float red[128];
    int b = blockIdx.x, head = blockIdx.y, t = threadIdx.x;
    for (int i = t; i < DN; i += 128) {
        emb[i] = g_hpool[b * DN + i];
        emb[DN + i] = g_opool[b * DN + i];
    }
    if (t < 32) emb[2*DN + t] = g_epool[b * 32 + t];
    __syncthreads();
    const float* Wp = head ? Wp2 : Wp1;
    const float* bp = head ? bp2 : bp1;
    float acc = -INFINITY;
    if (t < CNC) {
        acc = bp[t];
        for (int k = 0; k < 2*DN + 32; k++) acc += emb[k] * Wp[k * CNC + t];
    }
    red[t] = acc;
    __syncthreads();
    for (int s = 64; s > 0; s >>= 1) {
        if (t < s) red[t] = fmaxf(red[t], red[t + s]);
        __syncthreads();
    }
    float mx = red[0];
    __syncthreads();
    float ex = (t < CNC) ? __expf(acc - mx) : 0.f;
    red[t] = ex;
    __syncthreads();
    for (int s = 64; s > 0; s >>= 1) {
        if (t < s) red[t] += red[t + s];
        __syncthreads();
    }
    float sum = red[0];
    if (t < CNC) out[((size_t)b * 2 + head) * CNC + t] = ex / sum;
}

// ---------------- host ----------------
#define SYM(p, s) do { void* tmp__ = 0; cudaGetSymbolAddress(&tmp__, s); p = (decltype(p))tmp__; } while (0)

extern "C" void kernel_launch(void* const* d_in, const int* in_sizes, int n_in,
                              void* d_out, int out_size)
{
    const float* x_human  = (const float*)d_in[0];
    const float* x_object = (const float*)d_in[1];
    const int*   ei_ho    = (const int*)d_in[2];
    const int*   ei_oh    = (const int*)d_in[3];
    const float* ea_ho    = (const float*)d_in[4];
    const float* ea_oh    = (const float*)d_in[5];
    const int*   hbatch   = (const int*)d_in[6];
    const int*   obatch   = (const int*)d_in[7];
    const float* Wsrc_ho  = (const float*)d_in[8];
    const float* Wdst_ho  = (const float*)d_in[9];
    const float* asrc_ho  = (const float*)d_in[10];
    const float* adst_ho  = (const float*)d_in[11];
    const float* Wedge_ho = (const float*)d_in[12];
    const float* aedge_ho = (const float*)d_in[13];
    const float* bias_ho  = (const float*)d_in[14];
    const float* Wsrc_oh  = (const float*)d_in[15];
    const float* Wdst_oh  = (const float*)d_in[16];
    const float* asrc_oh  = (const float*)d_in[17];
    const float* adst_oh  = (const float*)d_in[18];
    const float* Wedge_oh = (const float*)d_in[19];
    const float* aedge_oh = (const float*)d_in[20];
    const float* bias_oh  = (const float*)d_in[21];
    const float* W_emlp   = (const float*)d_in[22];
    const float* b_emlp   = (const float*)d_in[23];
    const float* W_p1     = (const float*)d_in[24];
    const float* b_p1     = (const float*)d_in[25];
    const float* W_p2     = (const float*)d_in[26];
    const float* b_p2     = (const float*)d_in[27];

    float *xh0, *xo0, *agg_h, *agg_o;
    float *ex_ho, *ex_oh;
    float *as_ho, *ad_ho, *as_oh, *ad_oh;
    float *den_ho, *den_oh, *cvec;
    float *hpool, *opool, *epool;
    int *starts_h, *starts_o, *cnt_e;
    unsigned *Wh, *Wl, *Ahh, *All;
    SYM(xh0, g_xh);        SYM(xo0, g_xo);
    SYM(agg_h, g_agg_h);   SYM(agg_o, g_agg_o);
    SYM(ex_ho, g_ex_ho);   SYM(ex_oh, g_ex_oh);
    SYM(as_ho, g_as_ho); SYM(ad_ho, g_ad_ho);
    SYM(as_oh, g_as_oh); SYM(ad_oh, g_ad_oh);
    SYM(den_ho, g_den_ho); SYM(den_oh, g_den_oh);
    SYM(cvec, g_cvec);
    SYM(hpool, g_hpool); SYM(opool, g_opool); SYM(epool, g_epool);
    SYM(starts_h, g_starts_h); SYM(starts_o, g_starts_o); SYM(cnt_e, g_cnt_e);
    SYM(Wh, g_Wh); SYM(Wl, g_Wl); SYM(Ahh, g_Ahh); SYM(All, g_All);
    float* xh1 = xh0 + (size_t)NHN * DN;
    float* xo1 = xo0 + (size_t)NON * DN;

    cudaFuncSetAttribute(k_gemm_tc, cudaFuncAttributeMaxDynamicSharedMemorySize, GSMEM);

    cudaMemcpyAsync(xh0, x_human,  sizeof(float)*(size_t)NHN*DN, cudaMemcpyDeviceToDevice, 0);
    cudaMemcpyAsync(xo0, x_object, sizeof(float)*(size_t)NON*DN, cudaMemcpyDeviceToDevice, 0);

    // pre-split all weight matrices once
    k_convW<<<512, 256>>>(Wsrc_ho, Wsrc_oh);

    int nsBlocksH = (NHN * 32 + 255) / 256;
    int nsBlocksO = (NON * 32 + 255) / 256;
    int eBlocks   = (NEN + 255) / 256;
    int cBlocks   = (NEN * 32) / 256;
    int caBlocks  = (NON * 32 + 255) / 256;
    dim3 gg(2, (NON + 127) / 128);
    size_t WMAT = (size_t)(DN/2) * DN;

    int cur = 0;
    for (int l = 0; l < LN; l++) {
        float* xh_in  = cur ? xh1 : xh0;
        float* xh_out = cur ? xh0 : xh1;
        float* xo_in  = cur ? xo1 : xo0;
        float* xo_out = cur ? xo0 : xo1;

        k_small<<<1, 256>>>(Wsrc_ho, asrc_ho, Wdst_ho, adst_ho,
                            Wsrc_oh, asrc_oh, Wdst_oh, adst_oh,
                            Wedge_ho, aedge_ho, Wedge_oh, aedge_oh, l);
        cudaMemsetAsync(agg_h, 0, sizeof(float)*(size_t)NHN*DN, 0);
        cudaMemsetAsync(agg_o, 0, sizeof(float)*(size_t)NON*DN, 0);
        cudaMemsetAsync(den_ho,  0, sizeof(float)*NON, 0);
        cudaMemsetAsync(den_oh,  0, sizeof(float)*NHN, 0);

        k_nodescore<<<nsBlocksH, 256>>>(xh_in, 0, 3, as_ho, ad_oh, NHN);
        k_nodescore<<<nsBlocksO, 256>>>(xo_in, 2, 1, as_oh, ad_ho, NON);

        k_edgeAB<<<eBlocks, 256>>>(ei_ho, ei_ho + NEN, ea_ho, as_ho, ad_ho, cvec,     ex_ho, den_ho);
        k_edgeAB<<<eBlocks, 256>>>(ei_oh, ei_oh + NEN, ea_oh, as_oh, ad_oh, cvec + 2, ex_oh, den_oh);
        k_edgeC<<<cBlocks, 256>>>(ei_ho, ei_ho + NEN, ex_ho, den_ho, xh_in, agg_o);
        k_edgeC<<<cBlocks, 256>>>(ei_oh, ei_oh + NEN, ex_oh, den_oh, xo_in, agg_h);

        // relation ho: out_o = relu(agg_o @ Wsrc_ho[l]) [+resid]
        k_convA<<<caBlocks, 256>>>(agg_o, Ahh, All, NON * 32);
        k_gemm_tc<<<gg, 256, GSMEM>>>(Ahh, All, Wh + (size_t)l * WMAT, Wl + (size_t)l * WMAT,
                                      bias_ho + l*DN, l ? xo_in : (const float*)0, xo_out, NON);
        // relation oh: out_h = relu(agg_h @ Wsrc_oh[l]) [+resid]
        k_convA<<<caBlocks, 256>>>(agg_h, Ahh, All, NHN * 32);
        k_gemm_tc<<<gg, 256, GSMEM>>>(Ahh, All, Wh + (size_t)(LN + l) * WMAT, Wl + (size_t)(LN + l) * WMAT,
                                      bias_oh + l*DN, l ? xh_in : (const float*)0, xh_out, NHN);
        cur ^= 1;
    }
    float* xh_fin = cur ? xh1 : xh0;
    float* xo_fin = cur ? xo1 : xo0;

    k_starts<<<(NHN + 255) / 256, 256>>>(hbatch, starts_h, NHN);
    k_starts<<<(NON + 255) / 256, 256>>>(obatch, starts_o, NON);
    k_pool<<<BNB, 256>>>(xh_fin, starts_h, hpool);
    k_pool<<<BNB, 256>>>(xo_fin, starts_o, opool);

    cudaMemsetAsync(epool, 0, sizeof(float)*BNB*32, 0);
    cudaMemsetAsync(cnt_e, 0, sizeof(int)*BNB, 0);
    k_epool<<<512, 256>>>(ei_ho, ea_ho, hbatch, W_emlp, b_emlp);
    k_epool_div<<<(BNB*32 + 255) / 256, 256>>>();

    k_head<<<dim3(BNB, 2), 128>>>(W_p1, b_p1, W_p2, b_p2, (float*)d_out);
}

// round 11
// speedup vs baseline: 1.4015x; 1.4015x over previous
#include <cuda_runtime.h>
#include <cuda_fp16.h>
#include <math.h>

#define NHN 50000
#define NON 50000
#define NEN 500000
#define DN  256
#define LN  8
#define BNB 512
#define CNC 117

// ---------------- device scratch (static: allocation-free rule) ----------------
__device__ __align__(16) float g_xh[2][NHN*DN];
__device__ __align__(16) float g_xo[2][NON*DN];
__device__ __align__(16) float g_agg_h[NHN*DN];
__device__ __align__(16) float g_agg_o[NON*DN];
__device__ float g_ex_ho[NEN];
__device__ float g_ex_oh[NEN];
__device__ float g_as_ho[NHN];
__device__ float g_ad_ho[NON];
__device__ float g_as_oh[NON];
__device__ float g_ad_oh[NHN];
__device__ float g_den_ho[NON];
__device__ float g_den_oh[NHN];
__device__ __align__(16) float g_wvec[4][DN];
__device__ float g_cvec[4];
__device__ __align__(16) float g_hpool[BNB*DN];
__device__ __align__(16) float g_opool[BNB*DN];
__device__ float g_epool[BNB*32];
__device__ int g_starts_h[BNB+1];
__device__ int g_starts_o[BNB+1];
__device__ int g_cnt_e[BNB];
// fp16-split weight buffers (packed half2 along K)
__device__ __align__(16) unsigned g_Wh[2*LN*(DN/2)*DN];   // 2 MB
__device__ __align__(16) unsigned g_Wl[2*LN*(DN/2)*DN];

// ---------------- helpers ----------------
__device__ __forceinline__ void red_add4(float* p, float4 v) {
    asm volatile("red.global.add.v4.f32 [%0], {%1,%2,%3,%4};"
                 :: "l"(p), "f"(v.x), "f"(v.y), "f"(v.z), "f"(v.w) : "memory");
}
// split (a,b) -> packed half2 hi + half2 lo (2-term fp16 split, 22-bit effective)
__device__ __forceinline__ void split2(float a, float b, unsigned &hi, unsigned &lo) {
    __half ha = __float2half_rn(a), hb = __float2half_rn(b);
    __half la = __float2half_rn(a - __half2float(ha));
    __half lb = __float2half_rn(b - __half2float(hb));
    hi = (unsigned)__half_as_ushort(ha) | ((unsigned)__half_as_ushort(hb) << 16);
    lo = (unsigned)__half_as_ushort(la) | ((unsigned)__half_as_ushort(lb) << 16);
}
__device__ __forceinline__ void mma_f16(float* d, const unsigned* a, const unsigned* b) {
    asm volatile("mma.sync.aligned.m16n8k16.row.col.f32.f16.f16.f32 "
                 "{%0,%1,%2,%3}, {%4,%5,%6,%7}, {%8,%9}, {%0,%1,%2,%3};"
                 : "+f"(d[0]), "+f"(d[1]), "+f"(d[2]), "+f"(d[3])
                 : "r"(a[0]), "r"(a[1]), "r"(a[2]), "r"(a[3]),
                   "r"(b[0]), "r"(b[1]));
}
__device__ __forceinline__ void cp16(unsigned* dst, const unsigned* src) {
    unsigned d = (unsigned)__cvta_generic_to_shared(dst);
    asm volatile("cp.async.cg.shared.global [%0], [%1], 16;" :: "r"(d), "l"(src));
}
#define CP_COMMIT() asm volatile("cp.async.commit_group;")

// ---------------- weight pre-split: all 16 matrices -> packed half2 hi/lo
__global__ void k_convW(const float* __restrict__ Who, const float* __restrict__ Woh)
{
    int t = blockIdx.x * blockDim.x + threadIdx.x;      // 16*128*64 = 131072
    int m  = t >> 13;
    int r  = t & 8191;
    int k2 = r >> 6;
    int ng = r & 63;
    const float* W = ((m >> 3) ? Woh : Who) + (size_t)(m & 7) * DN * DN;
    float4 u0 = *(const float4*)&W[(size_t)(2*k2)     * DN + ng*4];
    float4 u1 = *(const float4*)&W[(size_t)(2*k2 + 1) * DN + ng*4];
    uint4 hi, lo;
    split2(u0.x, u1.x, hi.x, lo.x);
    split2(u0.y, u1.y, hi.y, lo.y);
    split2(u0.z, u1.z, hi.z, lo.z);
    split2(u0.w, u1.w, hi.w, lo.w);
    size_t o = (size_t)m * ((DN/2)*DN) + (size_t)k2 * DN + ng*4;
    *(uint4*)&g_Wh[o] = hi;
    *(uint4*)&g_Wl[o] = lo;
}

// ---------------- per-layer small weights (parallel: one warp per dot)
__global__ void k_small2(const float* __restrict__ WsrcHo, const float* __restrict__ asrcHo,
                         const float* __restrict__ WdstHo, const float* __restrict__ adstHo,
                         const float* __restrict__ WsrcOh, const float* __restrict__ asrcOh,
                         const float* __restrict__ WdstOh, const float* __restrict__ adstOh,
                         const float* __restrict__ WedgeHo, const float* __restrict__ aedgeHo,
                         const float* __restrict__ WedgeOh, const float* __restrict__ aedgeOh, int l)
{
    int gw = blockIdx.x * (blockDim.x >> 5) + (threadIdx.x >> 5);
    int lane = threadIdx.x & 31;
    if (gw < 1024) {
        int mat = gw >> 8, k = gw & 255;
        const float* W; const float* a;
        if (mat == 0)      { W = WsrcHo; a = asrcHo; }
        else if (mat == 1) { W = WdstHo; a = adstHo; }
        else if (mat == 2) { W = WsrcOh; a = asrcOh; }
        else               { W = WdstOh; a = adstOh; }
        const float4* Wr = (const float4*)(W + (size_t)l*DN*DN + (size_t)k*DN) + lane*2;
        const float4* ar = (const float4*)(a + l*DN) + lane*2;
        float4 w0 = Wr[0], w1 = Wr[1], a0 = ar[0], a1 = ar[1];
        float d = w0.x*a0.x + w0.y*a0.y + w0.z*a0.z + w0.w*a0.w
                + w1.x*a1.x + w1.y*a1.y + w1.z*a1.z + w1.w*a1.w;
        #pragma unroll
        for (int off = 16; off > 0; off >>= 1) d += __shfl_down_sync(0xffffffffu, d, off);
        if (lane == 0) g_wvec[mat][k] = d;
    } else if (gw < 1028) {
        int idx = gw - 1024;
        const float* We = (idx < 2) ? (WedgeHo + (size_t)l*2*DN + (size_t)idx*DN)
                                    : (WedgeOh + (size_t)l*2*DN + (size_t)(idx-2)*DN);
        const float* ae = ((idx < 2) ? aedgeHo : aedgeOh) + l*DN;
        const float4* Wr = (const float4*)We + lane*2;
        const float4* ar = (const float4*)ae + lane*2;
        float4 w0 = Wr[0], w1 = Wr[1], a0 = ar[0], a1 = ar[1];
        float d = w0.x*a0.x + w0.y*a0.y + w0.z*a0.z + w0.w*a0.w
                + w1.x*a1.x + w1.y*a1.y + w1.z*a1.z + w1.w*a1.w;
        #pragma unroll
        for (int off = 16; off > 0; off >>= 1) d += __shfl_down_sync(0xffffffffu, d, off);
        if (lane == 0) g_cvec[idx] = d;
    }
}

// ---------------- node scores: two dot products per node (warp per node)
__global__ void k_nodescore(const float* __restrict__ x, int ia, int ib,
                            float* __restrict__ outA, float* __restrict__ outB, int N)
{
    int w = (blockIdx.x * blockDim.x + threadIdx.x) >> 5;
    int lane = threadIdx.x & 31;
    if (w >= N) return;
    const float4* xr = (const float4*)(x + (size_t)w * DN);
    const float4* va = (const float4*)g_wvec[ia];
    const float4* vb = (const float4*)g_wvec[ib];
    float4 x0 = xr[lane], x1 = xr[lane + 32];
    float4 a0 = va[lane], a1 = va[lane + 32];
    float4 b0 = vb[lane], b1 = vb[lane + 32];
    float dA = x0.x*a0.x + x0.y*a0.y + x0.z*a0.z + x0.w*a0.w
             + x1.x*a1.x + x1.y*a1.y + x1.z*a1.z + x1.w*a1.w;
    float dB = x0.x*b0.x + x0.y*b0.y + x0.z*b0.z + x0.w*b0.w
             + x1.x*b1.x + x1.y*b1.y + x1.z*b1.z + x1.w*b1.w;
    #pragma unroll
    for (int off = 16; off > 0; off >>= 1) {
        dA += __shfl_down_sync(0xffffffffu, dA, off);
        dB += __shfl_down_sync(0xffffffffu, dB, off);
    }
    if (lane == 0) { outA[w] = dA; outB[w] = dB; }
}

// ---------------- fused edge pass: logit -> exp + segment sum
__global__ void k_edgeAB(const int* __restrict__ src, const int* __restrict__ dst,
                         const float* __restrict__ ea,
                         const float* __restrict__ a_s, const float* __restrict__ a_d,
                         const float* __restrict__ cpair,
                         float* __restrict__ ex, float* __restrict__ den)
{
    int e = blockIdx.x * blockDim.x + threadIdx.x;
    if (e >= NEN) return;
    int s = src[e], d = dst[e];
    float2 at = ((const float2*)ea)[e];
    float lg = a_s[s] + a_d[d] + at.x * cpair[0] + at.y * cpair[1];
    lg = (lg > 0.f) ? lg : 0.2f * lg;
    float v = __expf(lg);
    ex[e] = v;
    atomicAdd(&den[d], v);
}

// ---------------- edge pass C: weighted gather + scatter-add (warp per edge)
__global__ void k_edgeC(const int* __restrict__ src, const int* __restrict__ dst,
                        const float* __restrict__ ex, const float* __restrict__ den,
                        const float* __restrict__ x, float* __restrict__ agg)
{
    int e = (blockIdx.x * blockDim.x + threadIdx.x) >> 5;
    if (e >= NEN) return;
    int lane = threadIdx.x & 31;
    int s = src[e], d = dst[e];
    float w = ex[e] / den[d];
    const float4* xs = (const float4*)(x + (size_t)s * DN);
    float4 v0 = xs[lane], v1 = xs[lane + 32];
    v0.x *= w; v0.y *= w; v0.z *= w; v0.w *= w;
    v1.x *= w; v1.y *= w; v1.z *= w; v1.w *= w;
    float* base = agg + (size_t)d * DN;
    red_add4(base + lane * 4, v0);
    red_add4(base + 128 + lane * 4, v1);
}

// ---------------- tensor-core GEMM v4: fp32 A inline-split (prefetched), pre-split W via
// cp.async double buffer. out = relu(A@W + bias) [+ resid]; 128x128 tile, BK=32, 8 warps (2x4)
#define ASTR2 20
#define BSTR2 132
#define ASZ (128*ASTR2)
#define BSZ (16*BSTR2)
#define NCH (DN/32)
#define GSMEM ((4*ASZ + 4*BSZ) * 4)   // 74752 bytes

__global__ void __launch_bounds__(256, 2)
k_gemm_tc(const float* __restrict__ A,
          const unsigned* __restrict__ Wh, const unsigned* __restrict__ Wl,
          const float* __restrict__ bias, const float* __restrict__ resid,
          float* __restrict__ Cmat, int M)
{
    extern __shared__ unsigned sm[];
    unsigned* sAh = sm;
    unsigned* sAl = sm + 2*ASZ;
    unsigned* sBh = sm + 4*ASZ;
    unsigned* sBl = sm + 4*ASZ + 2*BSZ;

    int tid  = threadIdx.x;
    int lane = tid & 31;
    int warp = tid >> 5;
    int wRow = warp >> 2;
    int wCol = warp & 3;
    int rowBase = blockIdx.y * 128;
    int colBase = blockIdx.x * 128;

    float acc[4][4][4];
    #pragma unroll
    for (int i = 0; i < 4; i++)
        #pragma unroll
        for (int j = 0; j < 4; j++)
            #pragma unroll
            for (int k = 0; k < 4; k++) acc[i][j][k] = 0.f;

    // A staging: 2 threads per row, 16 floats each
    int arow = tid >> 1, ahalf = tid & 1;
    int gr = rowBase + arow;
    const float* gA = A + (size_t)gr * DN + ahalf * 16;
    bool aok = (gr < M);
    unsigned* dAh = sAh + arow * ASTR2 + ahalf * 8;
    unsigned* dAl = sAl + arow * ASTR2 + ahalf * 8;

    // B staging: 16 k2-rows, 8 words per thread
    int bk2 = tid >> 4, boff = (tid & 15) * 8;
    const unsigned* gBh = Wh + (size_t)bk2 * DN + colBase + boff;
    const unsigned* gBl = Wl + (size_t)bk2 * DN + colBase + boff;
    unsigned* dBh = sBh + bk2 * BSTR2 + boff;
    unsigned* dBl = sBl + bk2 * BSTR2 + boff;

    #define STAGEB(b, c) do { \
        cp16(dBh + (b)*BSZ,     gBh + (size_t)(c)*16*DN); \
        cp16(dBh + (b)*BSZ + 4, gBh + (size_t)(c)*16*DN + 4); \
        cp16(dBl + (b)*BSZ,     gBl + (size_t)(c)*16*DN); \
        cp16(dBl + (b)*BSZ + 4, gBl + (size_t)(c)*16*DN + 4); \
        CP_COMMIT(); \
    } while (0)

    float4 ra0, ra1, ra2, ra3;
    float4 z4 = make_float4(0.f, 0.f, 0.f, 0.f);
    if (aok) {
        ra0 = *(const float4*)gA;        ra1 = *(const float4*)(gA + 4);
        ra2 = *(const float4*)(gA + 8);  ra3 = *(const float4*)(gA + 12);
    } else { ra0 = ra1 = ra2 = ra3 = z4; }
    STAGEB(0, 0);

    int buf = 0;
    for (int c = 0; c < NCH; c++) {
        // convert & store A chunk c into buf
        uint4 h0, l0, h1, l1;
        split2(ra0.x, ra0.y, h0.x, l0.x);
        split2(ra0.z, ra0.w, h0.y, l0.y);
        split2(ra1.x, ra1.y, h0.z, l0.z);
        split2(ra1.z, ra1.w, h0.w, l0.w);
        split2(ra2.x, ra2.y, h1.x, l1.x);
        split2(ra2.z, ra2.w, h1.y, l1.y);
        split2(ra3.x, ra3.y, h1.z, l1.z);
        split2(ra3.z, ra3.w, h1.w, l1.w);
        *(uint4*)(dAh + buf*ASZ)     = h0;
        *(uint4*)(dAh + buf*ASZ + 4) = h1;
        *(uint4*)(dAl + buf*ASZ)     = l0;
        *(uint4*)(dAl + buf*ASZ + 4) = l1;
        if (c + 1 < NCH) {
            if (aok) {
                const float* g = gA + (c + 1) * 32;
                ra0 = *(const float4*)g;        ra1 = *(const float4*)(g + 4);
                ra2 = *(const float4*)(g + 8);  ra3 = *(const float4*)(g + 12);
            }
            STAGEB(buf ^ 1, c + 1);
            asm volatile("cp.async.wait_group 1;" ::: "memory");
        } else {
            asm volatile("cp.async.wait_group 0;" ::: "memory");
        }
        __syncthreads();
        const unsigned* Abh = sAh + buf * ASZ;
        const unsigned* Abl = sAl + buf * ASZ;
        const unsigned* Bbh = sBh + buf * BSZ;
        const unsigned* Bbl = sBl + buf * BSZ;
        #pragma unroll
        for (int s = 0; s < 2; s++) {
            int kk = s * 8 + (lane & 3);
            unsigned bhf[4][2], blf[4][2];
            #pragma unroll
            for (int nt = 0; nt < 4; nt++) {
                int n = wCol * 32 + nt * 8 + (lane >> 2);
                bhf[nt][0] = Bbh[kk * BSTR2 + n];       bhf[nt][1] = Bbh[(kk + 4) * BSTR2 + n];
                blf[nt][0] = Bbl[kk * BSTR2 + n];       blf[nt][1] = Bbl[(kk + 4) * BSTR2 + n];
            }
            #pragma unroll
            for (int mt = 0; mt < 4; mt++) {
                int r = wRow * 64 + mt * 16 + (lane >> 2);
                unsigned ahf[4], alf[4];
                ahf[0] = Abh[r * ASTR2 + kk];           ahf[1] = Abh[(r + 8) * ASTR2 + kk];
                ahf[2] = Abh[r * ASTR2 + kk + 4];       ahf[3] = Abh[(r + 8) * ASTR2 + kk + 4];
                alf[0] = Abl[r * ASTR2 + kk];           alf[1] = Abl[(r + 8) * ASTR2 + kk];
                alf[2] = Abl[r * ASTR2 + kk + 4];       alf[3] = Abl[(r + 8) * ASTR2 + kk + 4];
                #pragma unroll
                for (int nt = 0; nt < 4; nt++) {
                    mma_f16(acc[mt][nt], ahf, bhf[nt]);
                    mma_f16(acc[mt][nt], ahf, blf[nt]);
                    mma_f16(acc[mt][nt], alf, bhf[nt]);
                }
            }
        }
        __syncthreads();
        buf ^= 1;
    }

    // ---- epilogue: bias + relu [+ resid]
    #pragma unroll
    for (int mt = 0; mt < 4; mt++) {
        int r = rowBase + wRow * 64 + mt * 16 + (lane >> 2);
        #pragma unroll
        for (int nt = 0; nt < 4; nt++) {
            int c = colBase + wCol * 32 + nt * 8 + (lane & 3) * 2;
            float b0 = bias[c], b1 = bias[c + 1];
            if (r < M) {
                float v0 = fmaxf(acc[mt][nt][0] + b0, 0.f);
                float v1 = fmaxf(acc[mt][nt][1] + b1, 0.f);
                if (resid) {
                    float2 rv = *(const float2*)&resid[(size_t)r * DN + c];
                    v0 += rv.x; v1 += rv.y;
                }
                *(float2*)&Cmat[(size_t)r * DN + c] = make_float2(v0, v1);
            }
            int r2 = r + 8;
            if (r2 < M) {
                float v2 = fmaxf(acc[mt][nt][2] + b0, 0.f);
                float v3 = fmaxf(acc[mt][nt][3] + b1, 0.f);
                if (resid) {
                    float2 rv = *(const float2*)&resid[(size_t)r2 * DN + c];
                    v2 += rv.x; v3 += rv.y;
                }
                *(float2*)&Cmat[(size_t)r2 * DN + c] = make_float2(v2, v3);
            }
        }
    }
}

// ---------------- batch segment boundaries from sorted batch vector
__global__ void k_starts(const int* __restrict__ batch, int* __restrict__ starts, int N)
{
    int i = blockIdx.x * blockDim.x + threadIdx.x;
    if (i >= N) return;
    int b = batch[i];
    int prev = (i == 0) ? -1 : batch[i - 1];
    for (int v = prev + 1; v <= b; v++) starts[v] = i;
    if (i == N - 1)
        for (int v = b + 1; v <= BNB; v++) starts[v] = N;
}

// ---------------- segment-mean pooling (block per batch, thread per column)
__global__ void k_pool(const float* __restrict__ x, const int* __restrict__ starts,
                       float* __restrict__ pool)
{
    int b = blockIdx.x, c = threadIdx.x;
    int s0 = starts[b], s1 = starts[b + 1];
    float acc = 0.f;
    for (int i = s0; i < s1; i++) acc += x[(size_t)i * DN + c];
    pool[b * DN + c] = acc / fmaxf((float)(s1 - s0), 1.f);
}

// ---------------- edge MLP pooling (warp per edge, lane per output channel)
__global__ void k_epool(const int* __restrict__ src, const float* __restrict__ ea,
                        const int* __restrict__ hbatch,
                        const float* __restrict__ Wem, const float* __restrict__ bem)
{
    __shared__ int hist[BNB];
    for (int t = threadIdx.x; t < BNB; t += blockDim.x) hist[t] = 0;
    __syncthreads();
    int lane = threadIdx.x & 31;
    int wid = (blockIdx.x * blockDim.x + threadIdx.x) >> 5;
    int nw = (gridDim.x * blockDim.x) >> 5;
    float w0 = Wem[lane], w1 = Wem[32 + lane], bb = bem[lane];
    for (int e = wid; e < NEN; e += nw) {
        int b = hbatch[src[e]];
        float2 at = ((const float2*)ea)[e];
        float v = fmaxf(at.x * w0 + at.y * w1 + bb, 0.f);
        atomicAdd(&g_epool[b * 32 + lane], v);
        if (lane == 0) atomicAdd(&hist[b], 1);
    }
    __syncthreads();
    for (int t = threadIdx.x; t < BNB; t += blockDim.x)
        if (hist[t]) atomicAdd(&g_cnt_e[t], hist[t]);
}

__global__ void k_epool_div()
{
    int i = blockIdx.x * blockDim.x + threadIdx.x;
    if (i >= BNB * 32) return;
    g_epool[i] /= fmaxf((float)g_cnt_e[i >> 5], 1.f);
}

// ---------------- final heads: linear + softmax (block per (batch, head))
__global__ void k_head(const float* __restrict__ Wp1, const float* __restrict__ bp1,
                       const float* __restrict__ Wp2, const float* __restrict__ bp2,
                       float* __restrict__ out)
{
    __shared__ float emb[2*DN + 32];
    __shared__ float red[128];
    int b = blockIdx.x, head = blockIdx.y, t = threadIdx.x;
    for (int i = t; i < DN; i += 128) {
        emb[i] = g_hpool[b * DN + i];
        emb[DN + i] = g_opool[b * DN + i];
    }
    if (t < 32) emb[2*DN + t] = g_epool[b * 32 + t];
    __syncthreads();
    const float* Wp = head ? Wp2 : Wp1;
    const float* bp = head ? bp2 : bp1;
    float acc = -INFINITY;
    if (t < CNC) {
        acc = bp[t];
        for (int k = 0; k < 2*DN + 32; k++) acc += emb[k] * Wp[k * CNC + t];
    }
    red[t] = acc;
    __syncthreads();
    for (int s = 64; s > 0; s >>= 1) {
        if (t < s) red[t] = fmaxf(red[t], red[t + s]);
        __syncthreads();
    }
    float mx = red[0];
    __syncthreads();
    float ex = (t < CNC) ? __expf(acc - mx) : 0.f;
    red[t] = ex;
    __syncthreads();
    for (int s = 64; s > 0; s >>= 1) {
        if (t < s) red[t] += red[t + s];
        __syncthreads();
    }
    float sum = red[0];
    if (t < CNC) out[((size_t)b * 2 + head) * CNC + t] = ex / sum;
}

// ---------------- host ----------------
#define SYM(p, s) do { void* tmp__ = 0; cudaGetSymbolAddress(&tmp__, s); p = (decltype(p))tmp__; } while (0)

extern "C" void kernel_launch(void* const* d_in, const int* in_sizes, int n_in,
                              void* d_out, int out_size)
{
    const float* x_human  = (const float*)d_in[0];
    const float* x_object = (const float*)d_in[1];
    const int*   ei_ho    = (const int*)d_in[2];
    const int*   ei_oh    = (const int*)d_in[3];
    const float* ea_ho    = (const float*)d_in[4];
    const float* ea_oh    = (const float*)d_in[5];
    const int*   hbatch   = (const int*)d_in[6];
    const int*   obatch   = (const int*)d_in[7];
    const float* Wsrc_ho  = (const float*)d_in[8];
    const float* Wdst_ho  = (const float*)d_in[9];
    const float* asrc_ho  = (const float*)d_in[10];
    const float* adst_ho  = (const float*)d_in[11];
    const float* Wedge_ho = (const float*)d_in[12];
    const float* aedge_ho = (const float*)d_in[13];
    const float* bias_ho  = (const float*)d_in[14];
    const float* Wsrc_oh  = (const float*)d_in[15];
    const float* Wdst_oh  = (const float*)d_in[16];
    const float* asrc_oh  = (const float*)d_in[17];
    const float* adst_oh  = (const float*)d_in[18];
    const float* Wedge_oh = (const float*)d_in[19];
    const float* aedge_oh = (const float*)d_in[20];
    const float* bias_oh  = (const float*)d_in[21];
    const float* W_emlp   = (const float*)d_in[22];
    const float* b_emlp   = (const float*)d_in[23];
    const float* W_p1     = (const float*)d_in[24];
    const float* b_p1     = (const float*)d_in[25];
    const float* W_p2     = (const float*)d_in[26];
    const float* b_p2     = (const float*)d_in[27];

    float *xh0, *xo0, *agg_h, *agg_o;
    float *ex_ho, *ex_oh;
    float *as_ho, *ad_ho, *as_oh, *ad_oh;
    float *den_ho, *den_oh, *cvec;
    float *hpool, *opool, *epool;
    int *starts_h, *starts_o, *cnt_e;
    unsigned *Wh, *Wl;
    SYM(xh0, g_xh);        SYM(xo0, g_xo);
    SYM(agg_h, g_agg_h);   SYM(agg_o, g_agg_o);
    SYM(ex_ho, g_ex_ho);   SYM(ex_oh, g_ex_oh);
    SYM(as_ho, g_as_ho); SYM(ad_ho, g_ad_ho);
    SYM(as_oh, g_as_oh); SYM(ad_oh, g_ad_oh);
    SYM(den_ho, g_den_ho); SYM(den_oh, g_den_oh);
    SYM(cvec, g_cvec);
    SYM(hpool, g_hpool); SYM(opool, g_opool); SYM(epool, g_epool);
    SYM(starts_h, g_starts_h); SYM(starts_o, g_starts_o); SYM(cnt_e, g_cnt_e);
    SYM(Wh, g_Wh); SYM(Wl, g_Wl);
    float* xh1 = xh0 + (size_t)NHN * DN;
    float* xo1 = xo0 + (size_t)NON * DN;

    cudaFuncSetAttribute(k_gemm_tc, cudaFuncAttributeMaxDynamicSharedMemorySize, GSMEM);

    cudaMemcpyAsync(xh0, x_human,  sizeof(float)*(size_t)NHN*DN, cudaMemcpyDeviceToDevice, 0);
    cudaMemcpyAsync(xo0, x_object, sizeof(float)*(size_t)NON*DN, cudaMemcpyDeviceToDevice, 0);

    // pre-split all weight matrices once
    k_convW<<<512, 256>>>(Wsrc_ho, Wsrc_oh);

    int nsBlocksH = (NHN * 32 + 255) / 256;
    int nsBlocksO = (NON * 32 + 255) / 256;
    int eBlocks   = (NEN + 255) / 256;
    int cBlocks   = (NEN * 32) / 256;
    dim3 gg(2, (NON + 127) / 128);
    size_t WMAT = (size_t)(DN/2) * DN;

    int cur = 0;
    for (int l = 0; l < LN; l++) {
        float* xh_in  = cur ? xh1 : xh0;
        float* xh_out = cur ? xh0 : xh1;
        float* xo_in  = cur ? xo1 : xo0;
        float* xo_out = cur ? xo0 : xo1;

        k_small2<<<129, 256>>>(Wsrc_ho, asrc_ho, Wdst_ho, adst_ho,
                               Wsrc_oh, asrc_oh, Wdst_oh, adst_oh,
                               Wedge_ho, aedge_ho, Wedge_oh, aedge_oh, l);
        cudaMemsetAsync(agg_h, 0, sizeof(float)*(size_t)NHN*DN, 0);
        cudaMemsetAsync(agg_o, 0, sizeof(float)*(size_t)NON*DN, 0);
        cudaMemsetAsync(den_ho,  0, sizeof(float)*NON, 0);
        cudaMemsetAsync(den_oh,  0, sizeof(float)*NHN, 0);

        k_nodescore<<<nsBlocksH, 256>>>(xh_in, 0, 3, as_ho, ad_oh, NHN);
        k_nodescore<<<nsBlocksO, 256>>>(xo_in, 2, 1, as_oh, ad_ho, NON);

        k_edgeAB<<<eBlocks, 256>>>(ei_ho, ei_ho + NEN, ea_ho, as_ho, ad_ho, cvec,     ex_ho, den_ho);
        k_edgeAB<<<eBlocks, 256>>>(ei_oh, ei_oh + NEN, ea_oh, as_oh, ad_oh, cvec + 2, ex_oh, den_oh);
        k_edgeC<<<cBlocks, 256>>>(ei_ho, ei_ho + NEN, ex_ho, den_ho, xh_in, agg_o);
        k_edgeC<<<cBlocks, 256>>>(ei_oh, ei_oh + NEN, ex_oh, den_oh, xo_in, agg_h);

        k_gemm_tc<<<gg, 256, GSMEM>>>(agg_o, Wh + (size_t)l * WMAT, Wl + (size_t)l * WMAT,
                                      bias_ho + l*DN, l ? xo_in : (const float*)0, xo_out, NON);
        k_gemm_tc<<<gg, 256, GSMEM>>>(agg_h, Wh + (size_t)(LN + l) * WMAT, Wl + (size_t)(LN + l) * WMAT,
                                      bias_oh + l*DN, l ? xh_in : (const float*)0, xh_out, NHN);
        cur ^= 1;
    }
    float* xh_fin = cur ? xh1 : xh0;
    float* xo_fin = cur ? xo1 : xo0;

    k_starts<<<(NHN + 255) / 256, 256>>>(hbatch, starts_h, NHN);
    k_starts<<<(NON + 255) / 256, 256>>>(obatch, starts_o, NON);
    k_pool<<<BNB, 256>>>(xh_fin, starts_h, hpool);
    k_pool<<<BNB, 256>>>(xo_fin, starts_o, opool);

    cudaMemsetAsync(epool, 0, sizeof(float)*BNB*32, 0);
    cudaMemsetAsync(cnt_e, 0, sizeof(int)*BNB, 0);
    k_epool<<<512, 256>>>(ei_ho, ea_ho, hbatch, W_emlp, b_emlp);
    k_epool_div<<<(BNB*32 + 255) / 256, 256>>>();

    k_head<<<dim3(BNB, 2), 128>>>(W_p1, b_p1, W_p2, b_p2, (float*)d_out);
}

// round 13
// speedup vs baseline: 1.8665x; 1.3317x over previous
#include <cuda_runtime.h>
#include <cuda_fp16.h>
#include <math.h>

#define NHN 50000
#define NON 50000
#define NEN 500000
#define DN  256
#define LN  8
#define BNB 512
#define CNC 117

// ---------------- device scratch (static: allocation-free rule) ----------------
__device__ __align__(16) float g_xh[2][NHN*DN];
__device__ __align__(16) float g_xo[2][NON*DN];
__device__ __align__(16) float g_agg_h[NHN*DN];
__device__ __align__(16) float g_agg_o[NON*DN];
__device__ float g_as_ho[NHN];
__device__ float g_ad_ho[NON];
__device__ float g_as_oh[NON];
__device__ float g_ad_oh[NHN];
__device__ __align__(16) float g_wvec[4][DN];   // 0:wsa_ho 1:wda_ho 2:wsa_oh 3:wda_oh
__device__ float g_cvec[4];
__device__ __align__(16) float g_hpool[BNB*DN];
__device__ __align__(16) float g_opool[BNB*DN];
__device__ float g_epool[BNB*32];
__device__ int g_starts_h[BNB+1];
__device__ int g_starts_o[BNB+1];
__device__ int g_cnt_e[BNB];
// fp16-split weight buffers (packed half2 along K)
__device__ __align__(16) unsigned g_Wh[2*LN*(DN/2)*DN];   // 2 MB
__device__ __align__(16) unsigned g_Wl[2*LN*(DN/2)*DN];
// CSR (edges sorted by dst) — built once per launch, edge index is layer-invariant
__device__ int g_csr_start_ho[NON+1];
__device__ int g_csr_start_oh[NHN+1];
__device__ int g_esrc_ho[NEN];
__device__ int g_esrc_oh[NEN];
__device__ __align__(8) float2 g_eatt_ho[NEN];
__device__ __align__(8) float2 g_eatt_oh[NEN];
__device__ int g_deg_ho[NON];
__device__ int g_deg_oh[NHN];

// ---------------- helpers ----------------
__device__ __forceinline__ void split2(float a, float b, unsigned &hi, unsigned &lo) {
    __half ha = __float2half_rn(a), hb = __float2half_rn(b);
    __half la = __float2half_rn(a - __half2float(ha));
    __half lb = __float2half_rn(b - __half2float(hb));
    hi = (unsigned)__half_as_ushort(ha) | ((unsigned)__half_as_ushort(hb) << 16);
    lo = (unsigned)__half_as_ushort(la) | ((unsigned)__half_as_ushort(lb) << 16);
}
__device__ __forceinline__ void mma_f16(float* d, const unsigned* a, const unsigned* b) {
    asm volatile("mma.sync.aligned.m16n8k16.row.col.f32.f16.f16.f32 "
                 "{%0,%1,%2,%3}, {%4,%5,%6,%7}, {%8,%9}, {%0,%1,%2,%3};"
                 : "+f"(d[0]), "+f"(d[1]), "+f"(d[2]), "+f"(d[3])
                 : "r"(a[0]), "r"(a[1]), "r"(a[2]), "r"(a[3]),
                   "r"(b[0]), "r"(b[1]));
}
__device__ __forceinline__ void cp16(unsigned* dst, const unsigned* src) {
    unsigned d = (unsigned)__cvta_generic_to_shared(dst);
    asm volatile("cp.async.cg.shared.global [%0], [%1], 16;" :: "r"(d), "l"(src));
}
#define CP_COMMIT() asm volatile("cp.async.commit_group;")

// ---------------- weight pre-split: all 16 matrices -> packed half2 hi/lo
__global__ void k_convW(const float* __restrict__ Who, const float* __restrict__ Woh)
{
    int t = blockIdx.x * blockDim.x + threadIdx.x;      // 16*128*64 = 131072
    int m  = t >> 13;
    int r  = t & 8191;
    int k2 = r >> 6;
    int ng = r & 63;
    const float* W = ((m >> 3) ? Woh : Who) + (size_t)(m & 7) * DN * DN;
    float4 u0 = *(const float4*)&W[(size_t)(2*k2)     * DN + ng*4];
    float4 u1 = *(const float4*)&W[(size_t)(2*k2 + 1) * DN + ng*4];
    uint4 hi, lo;
    split2(u0.x, u1.x, hi.x, lo.x);
    split2(u0.y, u1.y, hi.y, lo.y);
    split2(u0.z, u1.z, hi.z, lo.z);
    split2(u0.w, u1.w, hi.w, lo.w);
    size_t o = (size_t)m * ((DN/2)*DN) + (size_t)k2 * DN + ng*4;
    *(uint4*)&g_Wh[o] = hi;
    *(uint4*)&g_Wl[o] = lo;
}

// ---------------- CSR build (once): degree count, scan, fill --------------------
__global__ void k_deg(const int* __restrict__ dst, int* __restrict__ deg)
{
    int e = blockIdx.x * blockDim.x + threadIdx.x;
    if (e < NEN) atomicAdd(&deg[dst[e]], 1);
}

// single-block exclusive scan of N ints -> starts[0..N]
__global__ void k_scan(const int* __restrict__ deg, int* __restrict__ starts, int N)
{
    __shared__ int ws[32];
    int t = threadIdx.x;
    const int CH = (N + 1023) / 1024;
    int base = t * CH;
    int s = 0;
    for (int i = 0; i < CH; i++) { int idx = base + i; if (idx < N) s += deg[idx]; }
    int lane = t & 31, w = t >> 5;
    int v = s;
    #pragma unroll
    for (int off = 1; off < 32; off <<= 1) {
        int u = __shfl_up_sync(0xffffffffu, v, off);
        if (lane >= off) v += u;
    }
    if (lane == 31) ws[w] = v;
    __syncthreads();
    if (w == 0) {
        int u = ws[lane];
        #pragma unroll
        for (int off = 1; off < 32; off <<= 1) {
            int q = __shfl_up_sync(0xffffffffu, u, off);
            if (lane >= off) u += q;
        }
        ws[lane] = u;
    }
    __syncthreads();
    int excl = v - s + (w ? ws[w-1] : 0);
    int run = excl;
    for (int i = 0; i < CH; i++) {
        int idx = base + i;
        if (idx < N) { starts[idx] = run; run += deg[idx]; }
    }
    if (t == 1023) starts[N] = run;
}

__global__ void k_fill(const int* __restrict__ src, const int* __restrict__ dst,
                       const float* __restrict__ ea, const int* __restrict__ starts,
                       int* __restrict__ cursor, int* __restrict__ esrc,
                       float2* __restrict__ eatt)
{
    int e = blockIdx.x * blockDim.x + threadIdx.x;
    if (e >= NEN) return;
    int d = dst[e];
    int pos = starts[d] + atomicAdd(&cursor[d], 1);
    esrc[pos] = src[e];
    eatt[pos] = ((const float2*)ea)[e];
}

// ---------------- per-layer small weights (warp per dot; 4 mats + edge vecs)
__global__ void k_small2(const float* __restrict__ WsrcHo, const float* __restrict__ asrcHo,
                         const float* __restrict__ WdstHo, const float* __restrict__ adstHo,
                         const float* __restrict__ WsrcOh, const float* __restrict__ asrcOh,
                         const float* __restrict__ WdstOh, const float* __restrict__ adstOh,
                         const float* __restrict__ WedgeHo, const float* __restrict__ aedgeHo,
                         const float* __restrict__ WedgeOh, const float* __restrict__ aedgeOh, int l)
{
    int gw = blockIdx.x * (blockDim.x >> 5) + (threadIdx.x >> 5);
    int lane = threadIdx.x & 31;
    if (gw < 1024) {
        int mat = gw >> 8, k = gw & 255;
        const float* W; const float* a;
        if (mat == 0)      { W = WsrcHo; a = asrcHo; }
        else if (mat == 1) { W = WdstHo; a = adstHo; }
        else if (mat == 2) { W = WsrcOh; a = asrcOh; }
        else               { W = WdstOh; a = adstOh; }
        const float4* Wr = (const float4*)(W + (size_t)l*DN*DN + (size_t)k*DN) + lane*2;
        const float4* ar = (const float4*)(a + l*DN) + lane*2;
        float4 w0 = Wr[0], w1 = Wr[1], a0 = ar[0], a1 = ar[1];
        float d = w0.x*a0.x + w0.y*a0.y + w0.z*a0.z + w0.w*a0.w
                + w1.x*a1.x + w1.y*a1.y + w1.z*a1.z + w1.w*a1.w;
        #pragma unroll
        for (int off = 16; off > 0; off >>= 1) d += __shfl_down_sync(0xffffffffu, d, off);
        if (lane == 0) g_wvec[mat][k] = d;
    } else if (gw < 1028) {
        int idx = gw - 1024;
        const float* We = (idx < 2) ? (WedgeHo + (size_t)l*2*DN + (size_t)idx*DN)
                                    : (WedgeOh + (size_t)l*2*DN + (size_t)(idx-2)*DN);
        const float* ae = ((idx < 2) ? aedgeHo : aedgeOh) + l*DN;
        const float4* Wr = (const float4*)We + lane*2;
        const float4* ar = (const float4*)ae + lane*2;
        float4 w0 = Wr[0], w1 = Wr[1], a0 = ar[0], a1 = ar[1];
        float d = w0.x*a0.x + w0.y*a0.y + w0.z*a0.z + w0.w*a0.w
                + w1.x*a1.x + w1.y*a1.y + w1.z*a1.z + w1.w*a1.w;
        #pragma unroll
        for (int off = 16; off > 0; off >>= 1) d += __shfl_down_sync(0xffffffffu, d, off);
        if (lane == 0) g_cvec[idx] = d;
    }
}

// ---------------- node scores: two dot products per node (warp per node)
__global__ void k_nodescore(const float* __restrict__ x, int ia, int ib,
                            float* __restrict__ outA, float* __restrict__ outB, int N)
{
    int w = (blockIdx.x * blockDim.x + threadIdx.x) >> 5;
    int lane = threadIdx.x & 31;
    if (w >= N) return;
    const float4* xr = (const float4*)(x + (size_t)w * DN);
    const float4* va = (const float4*)g_wvec[ia];
    const float4* vb = (const float4*)g_wvec[ib];
    float4 x0 = xr[lane], x1 = xr[lane + 32];
    float4 a0 = va[lane], a1 = va[lane + 32];
    float4 b0 = vb[lane], b1 = vb[lane + 32];
    float dA = x0.x*a0.x + x0.y*a0.y + x0.z*a0.z + x0.w*a0.w
             + x1.x*a1.x + x1.y*a1.y + x1.z*a1.z + x1.w*a1.w;
    float dB = x0.x*b0.x + x0.y*b0.y + x0.z*b0.z + x0.w*b0.w
             + x1.x*b1.x + x1.y*b1.y + x1.z*b1.z + x1.w*b1.w;
    #pragma unroll
    for (int off = 16; off > 0; off >>= 1) {
        dA += __shfl_down_sync(0xffffffffu, dA, off);
        dB += __shfl_down_sync(0xffffffffu, dB, off);
    }
    if (lane == 0) { outA[w] = dA; outB[w] = dB; }
}

// ---------------- fused segment softmax + weighted gather (warp per dst node)
// logit = leaky_relu(a_s[src] + a_d[dst] + ea.c)  — a_d does NOT cancel (leaky_relu!)
__global__ void k_agg(const int* __restrict__ starts, const int* __restrict__ esrc,
                      const float2* __restrict__ eatt,
                      const float* __restrict__ a_s, const float* __restrict__ a_d,
                      const float* __restrict__ cpair,
                      const float* __restrict__ x, float* __restrict__ agg, int N)
{
    int d = (blockIdx.x * blockDim.x + threadIdx.x) >> 5;
    if (d >= N) return;
    int lane = threadIdx.x & 31;
    int s0 = starts[d], s1 = starts[d + 1];
    float c0 = cpair[0], c1 = cpair[1];
    float ad = a_d[d];
    // pass A: softmax denominator
    float den = 0.f;
    for (int e = s0 + lane; e < s1; e += 32) {
        float2 at = eatt[e];
        float lg = a_s[esrc[e]] + ad + at.x * c0 + at.y * c1;
        lg = (lg > 0.f) ? lg : 0.2f * lg;
        den += __expf(lg);
    }
    #pragma unroll
    for (int off = 16; off > 0; off >>= 1)
        den += __shfl_xor_sync(0xffffffffu, den, off);
    float rden = (den > 0.f) ? 1.f / den : 0.f;
    // pass B: alpha-weighted gather of x rows
    float4 acc0 = make_float4(0.f,0.f,0.f,0.f);
    float4 acc1 = make_float4(0.f,0.f,0.f,0.f);
    for (int base = s0; base < s1; base += 32) {
        int e = base + lane;
        float ex = 0.f; int sv = 0;
        if (e < s1) {
            float2 at = eatt[e];
            sv = esrc[e];
            float lg = a_s[sv] + ad + at.x * c0 + at.y * c1;
            lg = (lg > 0.f) ? lg : 0.2f * lg;
            ex = __expf(lg);
        }
        int cnt = min(32, s1 - base);
        int j = 0;
        for (; j + 1 < cnt; j += 2) {
            float w0 = __shfl_sync(0xffffffffu, ex, j)     * rden;
            int   sA = __shfl_sync(0xffffffffu, sv, j);
            float w1 = __shfl_sync(0xffffffffu, ex, j + 1) * rden;
            int   sB = __shfl_sync(0xffffffffu, sv, j + 1);
            const float4* xa = (const float4*)(x + (size_t)sA * DN);
            const float4* xb = (const float4*)(x + (size_t)sB * DN);
            float4 a0 = xa[lane], a1 = xa[lane + 32];
            float4 b0 = xb[lane], b1 = xb[lane + 32];
            acc0.x += w0*a0.x + w1*b0.x; acc0.y += w0*a0.y + w1*b0.y;
            acc0.z += w0*a0.z + w1*b0.z; acc0.w += w0*a0.w + w1*b0.w;
            acc1.x += w0*a1.x + w1*b1.x; acc1.y += w0*a1.y + w1*b1.y;
            acc1.z += w0*a1.z + w1*b1.z; acc1.w += w0*a1.w + w1*b1.w;
        }
        if (j < cnt) {
            float w0 = __shfl_sync(0xffffffffu, ex, j) * rden;
            int   sA = __shfl_sync(0xffffffffu, sv, j);
            const float4* xa = (const float4*)(x + (size_t)sA * DN);
            float4 a0 = xa[lane], a1 = xa[lane + 32];
            acc0.x += w0*a0.x; acc0.y += w0*a0.y; acc0.z += w0*a0.z; acc0.w += w0*a0.w;
            acc1.x += w0*a1.x; acc1.y += w0*a1.y; acc1.z += w0*a1.z; acc1.w += w0*a1.w;
        }
    }
    float4* out = (float4*)(agg + (size_t)d * DN);
    out[lane] = acc0;
    out[lane + 32] = acc1;
}

// ---------------- tensor-core GEMM v4 (unchanged from R11 winner)
#define ASTR2 20
#define BSTR2 132
#define ASZ (128*ASTR2)
#define BSZ (16*BSTR2)
#define NCH (DN/32)
#define GSMEM ((4*ASZ + 4*BSZ) * 4)   // 74752 bytes

__global__ void __launch_bounds__(256, 2)
k_gemm_tc(const float* __restrict__ A,
          const unsigned* __restrict__ Wh, const unsigned* __restrict__ Wl,
          const float* __restrict__ bias, const float* __restrict__ resid,
          float* __restrict__ Cmat, int M)
{
    extern __shared__ unsigned sm[];
    unsigned* sAh = sm;
    unsigned* sAl = sm + 2*ASZ;
    unsigned* sBh = sm + 4*ASZ;
    unsigned* sBl = sm + 4*ASZ + 2*BSZ;

    int tid  = threadIdx.x;
    int lane = tid & 31;
    int warp = tid >> 5;
    int wRow = warp >> 2;
    int wCol = warp & 3;
    int rowBase = blockIdx.y * 128;
    int colBase = blockIdx.x * 128;

    float acc[4][4][4];
    #pragma unroll
    for (int i = 0; i < 4; i++)
        #pragma unroll
        for (int j = 0; j < 4; j++)
            #pragma unroll
            for (int k = 0; k < 4; k++) acc[i][j][k] = 0.f;

    int arow = tid >> 1, ahalf = tid & 1;
    int gr = rowBase + arow;
    const float* gA = A + (size_t)gr * DN + ahalf * 16;
    bool aok = (gr < M);
    unsigned* dAh = sAh + arow * ASTR2 + ahalf * 8;
    unsigned* dAl = sAl + arow * ASTR2 + ahalf * 8;

    int bk2 = tid >> 4, boff = (tid & 15) * 8;
    const unsigned* gBh = Wh + (size_t)bk2 * DN + colBase + boff;
    const unsigned* gBl = Wl + (size_t)bk2 * DN + colBase + boff;
    unsigned* dBh = sBh + bk2 * BSTR2 + boff;
    unsigned* dBl = sBl + bk2 * BSTR2 + boff;

    #define STAGEB(b, c) do { \
        cp16(dBh + (b)*BSZ,     gBh + (size_t)(c)*16*DN); \
        cp16(dBh + (b)*BSZ + 4, gBh + (size_t)(c)*16*DN + 4); \
        cp16(dBl + (b)*BSZ,     gBl + (size_t)(c)*16*DN); \
        cp16(dBl + (b)*BSZ + 4, gBl + (size_t)(c)*16*DN + 4); \
        CP_COMMIT(); \
    } while (0)

    float4 ra0, ra1, ra2, ra3;
    float4 z4 = make_float4(0.f, 0.f, 0.f, 0.f);
    if (aok) {
        ra0 = *(const float4*)gA;        ra1 = *(const float4*)(gA + 4);
        ra2 = *(const float4*)(gA + 8);  ra3 = *(const float4*)(gA + 12);
    } else { ra0 = ra1 = ra2 = ra3 = z4; }
    STAGEB(0, 0);

    int buf = 0;
    for (int c = 0; c < NCH; c++) {
        uint4 h0, l0, h1, l1;
        split2(ra0.x, ra0.y, h0.x, l0.x);
        split2(ra0.z, ra0.w, h0.y, l0.y);
        split2(ra1.x, ra1.y, h0.z, l0.z);
        split2(ra1.z, ra1.w, h0.w, l0.w);
        split2(ra2.x, ra2.y, h1.x, l1.x);
        split2(ra2.z, ra2.w, h1.y, l1.y);
        split2(ra3.x, ra3.y, h1.z, l1.z);
        split2(ra3.z, ra3.w, h1.w, l1.w);
        *(uint4*)(dAh + buf*ASZ)     = h0;
        *(uint4*)(dAh + buf*ASZ + 4) = h1;
        *(uint4*)(dAl + buf*ASZ)     = l0;
        *(uint4*)(dAl + buf*ASZ + 4) = l1;
        if (c + 1 < NCH) {
            if (aok) {
                const float* g = gA + (c + 1) * 32;
                ra0 = *(const float4*)g;        ra1 = *(const float4*)(g + 4);
                ra2 = *(const float4*)(g + 8);  ra3 = *(const float4*)(g + 12);
            }
            STAGEB(buf ^ 1, c + 1);
            asm volatile("cp.async.wait_group 1;" ::: "memory");
        } else {
            asm volatile("cp.async.wait_group 0;" ::: "memory");
        }
        __syncthreads();
        const unsigned* Abh = sAh + buf * ASZ;
        const unsigned* Abl = sAl + buf * ASZ;
        const unsigned* Bbh = sBh + buf * BSZ;
        const unsigned* Bbl = sBl + buf * BSZ;
        #pragma unroll
        for (int s = 0; s < 2; s++) {
            int kk = s * 8 + (lane & 3);
            unsigned bhf[4][2], blf[4][2];
            #pragma unroll
            for (int nt = 0; nt < 4; nt++) {
                int n = wCol * 32 + nt * 8 + (lane >> 2);
                bhf[nt][0] = Bbh[kk * BSTR2 + n];       bhf[nt][1] = Bbh[(kk + 4) * BSTR2 + n];
                blf[nt][0] = Bbl[kk * BSTR2 + n];       blf[nt][1] = Bbl[(kk + 4) * BSTR2 + n];
            }
            #pragma unroll
            for (int mt = 0; mt < 4; mt++) {
                int r = wRow * 64 + mt * 16 + (lane >> 2);
                unsigned ahf[4], alf[4];
                ahf[0] = Abh[r * ASTR2 + kk];           ahf[1] = Abh[(r + 8) * ASTR2 + kk];
                ahf[2] = Abh[r * ASTR2 + kk + 4];       ahf[3] = Abh[(r + 8) * ASTR2 + kk + 4];
                alf[0] = Abl[r * ASTR2 + kk];           alf[1] = Abl[(r + 8) * ASTR2 + kk];
                alf[2] = Abl[r * ASTR2 + kk + 4];       alf[3] = Abl[(r + 8) * ASTR2 + kk + 4];
                #pragma unroll
                for (int nt = 0; nt < 4; nt++) {
                    mma_f16(acc[mt][nt], ahf, bhf[nt]);
                    mma_f16(acc[mt][nt], ahf, blf[nt]);
                    mma_f16(acc[mt][nt], alf, bhf[nt]);
                }
            }
        }
        __syncthreads();
        buf ^= 1;
    }

    #pragma unroll
    for (int mt = 0; mt < 4; mt++) {
        int r = rowBase + wRow * 64 + mt * 16 + (lane >> 2);
        #pragma unroll
        for (int nt = 0; nt < 4; nt++) {
            int c = colBase + wCol * 32 + nt * 8 + (lane & 3) * 2;
            float b0 = bias[c], b1 = bias[c + 1];
            if (r < M) {
                float v0 = fmaxf(acc[mt][nt][0] + b0, 0.f);
                float v1 = fmaxf(acc[mt][nt][1] + b1, 0.f);
                if (resid) {
                    float2 rv = *(const float2*)&resid[(size_t)r * DN + c];
                    v0 += rv.x; v1 += rv.y;
                }
                *(float2*)&Cmat[(size_t)r * DN + c] = make_float2(v0, v1);
            }
            int r2 = r + 8;
            if (r2 < M) {
                float v2 = fmaxf(acc[mt][nt][2] + b0, 0.f);
                float v3 = fmaxf(acc[mt][nt][3] + b1, 0.f);
                if (resid) {
                    float2 rv = *(const float2*)&resid[(size_t)r2 * DN + c];
                    v2 += rv.x; v3 += rv.y;
                }
                *(float2*)&Cmat[(size_t)r2 * DN + c] = make_float2(v2, v3);
            }
        }
    }
}

// ---------------- batch segment boundaries from sorted batch vector
__global__ void k_starts(const int* __restrict__ batch, int* __restrict__ starts, int N)
{
    int i = blockIdx.x * blockDim.x + threadIdx.x;
    if (i >= N) return;
    int b = batch[i];
    int prev = (i == 0) ? -1 : batch[i - 1];
    for (int v = prev + 1; v <= b; v++) starts[v] = i;
    if (i == N - 1)
        for (int v = b + 1; v <= BNB; v++) starts[v] = N;
}

// ---------------- segment-mean pooling (block per batch, thread per column)
__global__ void k_pool(const float* __restrict__ x, const int* __restrict__ starts,
                       float* __restrict__ pool)
{
    int b = blockIdx.x, c = threadIdx.x;
    int s0 = starts[b], s1 = starts[b + 1];
    float acc = 0.f;
    for (int i = s0; i < s1; i++) acc += x[(size_t)i * DN + c];
    pool[b * DN + c] = acc / fmaxf((float)(s1 - s0), 1.f);
}

// ---------------- edge MLP pooling (warp per edge, lane per output channel)
__global__ void k_epool(const int* __restrict__ src, const float* __restrict__ ea,
                        const int* __restrict__ hbatch,
                        const float* __restrict__ Wem, const float* __restrict__ bem)
{
    __shared__ int hist[BNB];
    for (int t = threadIdx.x; t < BNB; t += blockDim.x) hist[t] = 0;
    __syncthreads();
    int lane = threadIdx.x & 31;
    int wid = (blockIdx.x * blockDim.x + threadIdx.x) >> 5;
    int nw = (gridDim.x * blockDim.x) >> 5;
    float w0 = Wem[lane], w1 = Wem[32 + lane], bb = bem[lane];
    for (int e = wid; e < NEN; e += nw) {
        int b = hbatch[src[e]];
        float2 at = ((const float2*)ea)[e];
        float v = fmaxf(at.x * w0 + at.y * w1 + bb, 0.f);
        atomicAdd(&g_epool[b * 32 + lane], v);
        if (lane == 0) atomicAdd(&hist[b], 1);
    }
    __syncthreads();
    for (int t = threadIdx.x; t < BNB; t += blockDim.x)
        if (hist[t]) atomicAdd(&g_cnt_e[t], hist[t]);
}

__global__ void k_epool_div()
{
    int i = blockIdx.x * blockDim.x + threadIdx.x;
    if (i >= BNB * 32) return;
    g_epool[i] /= fmaxf((float)g_cnt_e[i >> 5], 1.f);
}

// ---------------- final heads: linear + softmax (block per (batch, head))
__global__ void k_head(const float* __restrict__ Wp1, const float* __restrict__ bp1,
                       const float* __restrict__ Wp2, const float* __restrict__ bp2,
                       float* __restrict__ out)
{
    __shared__ float emb[2*DN + 32];
    __shared__ float red[128];
    int b = blockIdx.x, head = blockIdx.y, t = threadIdx.x;
    for (int i = t; i < DN; i += 128) {
        emb[i] = g_hpool[b * DN + i];
        emb[DN + i] = g_opool[b * DN + i];
    }
    if (t < 32) emb[2*DN + t] = g_epool[b * 32 + t];
    __syncthreads();
    const float* Wp = head ? Wp2 : Wp1;
    const float* bp = head ? bp2 : bp1;
    float acc = -INFINITY;
    if (t < CNC) {
        acc = bp[t];
        for (int k = 0; k < 2*DN + 32; k++) acc += emb[k] * Wp[k * CNC + t];
    }
    red[t] = acc;
    __syncthreads();
    for (int s = 64; s > 0; s >>= 1) {
        if (t < s) red[t] = fmaxf(red[t], red[t + s]);
        __syncthreads();
    }
    float mx = red[0];
    __syncthreads();
    float ex = (t < CNC) ? __expf(acc - mx) : 0.f;
    red[t] = ex;
    __syncthreads();
    for (int s = 64; s > 0; s >>= 1) {
        if (t < s) red[t] += red[t + s];
        __syncthreads();
    }
    float sum = red[0];
    if (t < CNC) out[((size_t)b * 2 + head) * CNC + t] = ex / sum;
}

// ---------------- host ----------------
#define SYM(p, s) do { void* tmp__ = 0; cudaGetSymbolAddress(&tmp__, s); p = (decltype(p))tmp__; } while (0)

extern "C" void kernel_launch(void* const* d_in, const int* in_sizes, int n_in,
                              void* d_out, int out_size)
{
    const float* x_human  = (const float*)d_in[0];
    const float* x_object = (const float*)d_in[1];
    const int*   ei_ho    = (const int*)d_in[2];
    const int*   ei_oh    = (const int*)d_in[3];
    const float* ea_ho    = (const float*)d_in[4];
    const float* ea_oh    = (const float*)d_in[5];
    const int*   hbatch   = (const int*)d_in[6];
    const int*   obatch   = (const int*)d_in[7];
    const float* Wsrc_ho  = (const float*)d_in[8];
    const float* Wdst_ho  = (const float*)d_in[9];
    const float* asrc_ho  = (const float*)d_in[10];
    const float* adst_ho  = (const float*)d_in[11];
    const float* Wedge_ho = (const float*)d_in[12];
    const float* aedge_ho = (const float*)d_in[13];
    const float* bias_ho  = (const float*)d_in[14];
    const float* Wsrc_oh  = (const float*)d_in[15];
    const float* Wdst_oh  = (const float*)d_in[16];
    const float* asrc_oh  = (const float*)d_in[17];
    const float* adst_oh  = (const float*)d_in[18];
    const float* Wedge_oh = (const float*)d_in[19];
    const float* aedge_oh = (const float*)d_in[20];
    const float* bias_oh  = (const float*)d_in[21];
    const float* W_emlp   = (const float*)d_in[22];
    const float* b_emlp   = (const float*)d_in[23];
    const float* W_p1     = (const float*)d_in[24];
    const float* b_p1     = (const float*)d_in[25];
    const float* W_p2     = (const float*)d_in[26];
    const float* b_p2     = (const float*)d_in[27];

    float *xh0, *xo0, *agg_h, *agg_o;
    float *as_ho, *ad_ho, *as_oh, *ad_oh, *cvec;
    float *hpool, *opool, *epool;
    int *starts_h, *starts_o, *cnt_e;
    unsigned *Wh, *Wl;
    int *cs_ho, *cs_oh, *esrc_ho, *esrc_oh, *deg_ho, *deg_oh;
    float2 *eatt_ho, *eatt_oh;
    SYM(xh0, g_xh);        SYM(xo0, g_xo);
    SYM(agg_h, g_agg_h);   SYM(agg_o, g_agg_o);
    SYM(as_ho, g_as_ho);   SYM(ad_ho, g_ad_ho);
    SYM(as_oh, g_as_oh);   SYM(ad_oh, g_ad_oh);
    SYM(cvec, g_cvec);
    SYM(hpool, g_hpool); SYM(opool, g_opool); SYM(epool, g_epool);
    SYM(starts_h, g_starts_h); SYM(starts_o, g_starts_o); SYM(cnt_e, g_cnt_e);
    SYM(Wh, g_Wh); SYM(Wl, g_Wl);
    SYM(cs_ho, g_csr_start_ho); SYM(cs_oh, g_csr_start_oh);
    SYM(esrc_ho, g_esrc_ho); SYM(esrc_oh, g_esrc_oh);
    SYM(eatt_ho, g_eatt_ho); SYM(eatt_oh, g_eatt_oh);
    SYM(deg_ho, g_deg_ho); SYM(deg_oh, g_deg_oh);
    float* xh1 = xh0 + (size_t)NHN * DN;
    float* xo1 = xo0 + (size_t)NON * DN;

    cudaFuncSetAttribute(k_gemm_tc, cudaFuncAttributeMaxDynamicSharedMemorySize, GSMEM);

    cudaMemcpyAsync(xh0, x_human,  sizeof(float)*(size_t)NHN*DN, cudaMemcpyDeviceToDevice, 0);
    cudaMemcpyAsync(xo0, x_object, sizeof(float)*(size_t)NON*DN, cudaMemcpyDeviceToDevice, 0);

    // one-time: weight pre-split + CSR build for both relations
    k_convW<<<512, 256>>>(Wsrc_ho, Wsrc_oh);
    int eBlocks = (NEN + 255) / 256;
    cudaMemsetAsync(deg_ho, 0, sizeof(int)*NON, 0);
    cudaMemsetAsync(deg_oh, 0, sizeof(int)*NHN, 0);
    k_deg<<<eBlocks, 256>>>(ei_ho + NEN, deg_ho);
    k_deg<<<eBlocks, 256>>>(ei_oh + NEN, deg_oh);
    k_scan<<<1, 1024>>>(deg_ho, cs_ho, NON);
    k_scan<<<1, 1024>>>(deg_oh, cs_oh, NHN);
    cudaMemsetAsync(deg_ho, 0, sizeof(int)*NON, 0);
    cudaMemsetAsync(deg_oh, 0, sizeof(int)*NHN, 0);
    k_fill<<<eBlocks, 256>>>(ei_ho, ei_ho + NEN, ea_ho, cs_ho, deg_ho, esrc_ho, eatt_ho);
    k_fill<<<eBlocks, 256>>>(ei_oh, ei_oh + NEN, ea_oh, cs_oh, deg_oh, esrc_oh, eatt_oh);

    int nsBlocksH = (NHN * 32 + 255) / 256;
    int nsBlocksO = (NON * 32 + 255) / 256;
    dim3 gg(2, (NON + 127) / 128);
    size_t WMAT = (size_t)(DN/2) * DN;

    int cur = 0;
    for (int l = 0; l < LN; l++) {
        float* xh_in  = cur ? xh1 : xh0;
        float* xh_out = cur ? xh0 : xh1;
        float* xo_in  = cur ? xo1 : xo0;
        float* xo_out = cur ? xo0 : xo1;

        k_small2<<<129, 256>>>(Wsrc_ho, asrc_ho, Wdst_ho, adst_ho,
                               Wsrc_oh, asrc_oh, Wdst_oh, adst_oh,
                               Wedge_ho, aedge_ho, Wedge_oh, aedge_oh, l);

        k_nodescore<<<nsBlocksH, 256>>>(xh_in, 0, 3, as_ho, ad_oh, NHN);
        k_nodescore<<<nsBlocksO, 256>>>(xo_in, 2, 1, as_oh, ad_ho, NON);

        // ho: aggregate xh rows into agg_o (per object node); a_d = ad_ho (object side)
        k_agg<<<nsBlocksO, 256>>>(cs_ho, esrc_ho, eatt_ho, as_ho, ad_ho, cvec,     xh_in, agg_o, NON);
        // oh: aggregate xo rows into agg_h (per human node); a_d = ad_oh (human side)
        k_agg<<<nsBlocksH, 256>>>(cs_oh, esrc_oh, eatt_oh, as_oh, ad_oh, cvec + 2, xo_in, agg_h, NHN);

        k_gemm_tc<<<gg, 256, GSMEM>>>(agg_o, Wh + (size_t)l * WMAT, Wl + (size_t)l * WMAT,
                                      bias_ho + l*DN, l ? xo_in : (const float*)0, xo_out, NON);
        k_gemm_tc<<<gg, 256, GSMEM>>>(agg_h, Wh + (size_t)(LN + l) * WMAT, Wl + (size_t)(LN + l) * WMAT,
                                      bias_oh + l*DN, l ? xh_in : (const float*)0, xh_out, NHN);
        cur ^= 1;
    }
    float* xh_fin = cur ? xh1 : xh0;
    float* xo_fin = cur ? xo1 : xo0;

    k_starts<<<(NHN + 255) / 256, 256>>>(hbatch, starts_h, NHN);
    k_starts<<<(NON + 255) / 256, 256>>>(obatch, starts_o, NON);
    k_pool<<<BNB, 256>>>(xh_fin, starts_h, hpool);
    k_pool<<<BNB, 256>>>(xo_fin, starts_o, opool);

    cudaMemsetAsync(epool, 0, sizeof(float)*BNB*32, 0);
    cudaMemsetAsync(cnt_e, 0, sizeof(int)*BNB, 0);
    k_epool<<<512, 256>>>(ei_ho, ea_ho, hbatch, W_emlp, b_emlp);
    k_epool_div<<<(BNB*32 + 255) / 256, 256>>>();

    k_head<<<dim3(BNB, 2), 128>>>(W_p1, b_p1, W_p2, b_p2, (float*)d_out);
}